// round 15
// baseline (speedup 1.0000x reference)
#include <cuda_runtime.h>
#include <cuda_fp16.h>
#include <cstdint>

#define T_DIM 1024
#define BT 128
#define BS 64
#define KS 72            // Kh f16x2 tile stride (u32): QK lane banks 8*m4+g distinct
#define VS 36            // Vh f16x2 tile stride (u32): PV lane banks 4*g+m4 distinct
#define FBUF (32 * KS + 64 * VS)   // 4608 u32 per f16 buffer

// bit-packed mask: 8 batches x 1024 rows x 1024 bits = 1 MB
__device__ __align__(16) uint32_t g_maskbits[8u * 1024u * 32u];

__device__ __forceinline__ float ex2(float x) {
    float r; asm("ex2.approx.f32 %0, %1;" : "=f"(r) : "f"(x)); return r;
}
__device__ __forceinline__ uint32_t packh2(float lo, float hi) {
    __half2 h = __floats2half2_rn(lo, hi);   // .x = lo (low 16 bits)
    return *(uint32_t*)&h;
}

__device__ __forceinline__ void mma_f16(float d[4], const uint32_t a[4],
                                        uint32_t b0, uint32_t b1) {
    asm volatile(
        "mma.sync.aligned.m16n8k16.row.col.f32.f16.f16.f32 "
        "{%0,%1,%2,%3}, {%4,%5,%6,%7}, {%8,%9}, {%0,%1,%2,%3};\n"
        : "+f"(d[0]), "+f"(d[1]), "+f"(d[2]), "+f"(d[3])
        : "r"(a[0]), "r"(a[1]), "r"(a[2]), "r"(a[3]), "r"(b0), "r"(b1));
}

// ---------------- mask pre-pack (int32 -> bits) ----------------
__global__ void pack_mask_bits_kernel(const int* __restrict__ m) {
    uint32_t w = blockIdx.x * 256 + threadIdx.x;
    const int4* p = (const int4*)(m + (size_t)w * 32);
    uint32_t bits = 0;
    #pragma unroll
    for (int j = 0; j < 8; j++) {
        int4 v = p[j];
        bits |= (v.x != 0 ? 1u : 0u) << (4 * j + 0);
        bits |= (v.y != 0 ? 1u : 0u) << (4 * j + 1);
        bits |= (v.z != 0 ? 1u : 0u) << (4 * j + 2);
        bits |= (v.w != 0 ? 1u : 0u) << (4 * j + 3);
    }
    g_maskbits[w] = bits;
}

__global__ __launch_bounds__(128, 2) void attn_flash_kernel(
    const float* __restrict__ qkv,
    const float* __restrict__ qk_bias,
    float* __restrict__ out)
{
    extern __shared__ __align__(16) uint32_t sh[];   // 2 x FBUF u32 (f16x2 tiles)

    const int tid = threadIdx.x;
    const int lane = tid & 31;
    const int g = lane >> 2;
    const int m4 = lane & 3;

    const int tile_t = blockIdx.x;   // 0..7
    const int bh = blockIdx.y;       // 0..127

    const float* qp = qkv + (size_t)bh * 192 * T_DIM;
    const float* kp = qp + 64 * T_DIM;
    const float* vp = qp + 128 * T_DIM;
    const uint32_t* mb = g_maskbits + (size_t)(bh & 7) * 1024u * 32u;

    const int t0 = tile_t * BT + (tid >> 5) * 32;
    const float bias2 = qk_bias[0] * 1.4426950408889634f;
    const float scale2 = 0.125f * 1.4426950408889634f;

    // mask row bases (fixed across stages)
    const uint32_t* mrow0l = mb + (size_t)(t0 + g) * 32;
    const uint32_t* mrow0h = mb + (size_t)(t0 + g + 8) * 32;
    const uint32_t* mrow1l = mb + (size_t)(t0 + 16 + g) * 32;
    const uint32_t* mrow1h = mb + (size_t)(t0 + 24 + g) * 32;

    // ---- Q fragments (fp16 m16n8k16 A layout), loaded once ----
    uint32_t qf[2][4][4];
    #pragma unroll
    for (int r = 0; r < 2; r++) {
        const int t = t0 + 16 * r + g;
        #pragma unroll
        for (int k4 = 0; k4 < 4; k4++) {
            const int c0 = 16 * k4 + 2 * m4;
            qf[r][k4][0] = packh2(qp[(size_t)c0 * T_DIM + t],           qp[(size_t)(c0 + 1) * T_DIM + t]);
            qf[r][k4][1] = packh2(qp[(size_t)c0 * T_DIM + t + 8],       qp[(size_t)(c0 + 1) * T_DIM + t + 8]);
            qf[r][k4][2] = packh2(qp[(size_t)(c0 + 8) * T_DIM + t],     qp[(size_t)(c0 + 9) * T_DIM + t]);
            qf[r][k4][3] = packh2(qp[(size_t)(c0 + 8) * T_DIM + t + 8], qp[(size_t)(c0 + 9) * T_DIM + t + 8]);
        }
    }

    float o[2][8][4];
    #pragma unroll
    for (int r = 0; r < 2; r++)
        #pragma unroll
        for (int n = 0; n < 8; n++)
            { o[r][n][0]=0.f; o[r][n][1]=0.f; o[r][n][2]=0.f; o[r][n][3]=0.f; }
    float lr[2]  = {0.f, 0.f};
    float lrh[2] = {0.f, 0.f};

    // ---- staging state: f32 prefetch regs + f16-packed regs ----
    float4 kA[4], kB[4], vA[4], vB[4];   // 64 f32
    uint32_t kw[16], vw[16];             // packed f16x2

    // per-thread task coords (fixed)
    const int kc2[4] = { (tid) >> 4, (tid + 128) >> 4, (tid + 256) >> 4, (tid + 384) >> 4 };
    const int ksq = tid & 15;
    const int vc[4]  = { (tid) >> 3, (tid + 128) >> 3, (tid + 256) >> 3, (tid + 384) >> 3 };
    const int vo = tid & 7;

    auto ldg_stage = [&](int stg) {
        const int s0 = stg * BS;
        #pragma unroll
        for (int it = 0; it < 4; it++) {
            kA[it] = *(const float4*)(kp + (size_t)(2 * kc2[it]) * T_DIM + s0 + 4 * ksq);
            kB[it] = *(const float4*)(kp + (size_t)(2 * kc2[it] + 1) * T_DIM + s0 + 4 * ksq);
            vA[it] = *(const float4*)(vp + (size_t)vc[it] * T_DIM + s0 + 8 * vo);
            vB[it] = *(const float4*)(vp + (size_t)vc[it] * T_DIM + s0 + 8 * vo + 4);
        }
    };
    auto cvt_stage = [&]() {
        #pragma unroll
        for (int it = 0; it < 4; it++) {
            kw[4*it+0] = packh2(kA[it].x, kB[it].x);
            kw[4*it+1] = packh2(kA[it].y, kB[it].y);
            kw[4*it+2] = packh2(kA[it].z, kB[it].z);
            kw[4*it+3] = packh2(kA[it].w, kB[it].w);
            vw[4*it+0] = packh2(vA[it].x, vA[it].y);
            vw[4*it+1] = packh2(vA[it].z, vA[it].w);
            vw[4*it+2] = packh2(vB[it].x, vB[it].y);
            vw[4*it+3] = packh2(vB[it].z, vB[it].w);
        }
    };
    auto sts_stage = [&](uint32_t* buf) {
        uint32_t* Kh = buf;
        uint32_t* Vh = buf + 32 * KS;
        #pragma unroll
        for (int it = 0; it < 4; it++) {
            *(uint4*)&Kh[kc2[it] * KS + 4 * ksq] =
                make_uint4(kw[4*it+0], kw[4*it+1], kw[4*it+2], kw[4*it+3]);
            *(uint4*)&Vh[vc[it] * VS + 4 * vo] =
                make_uint4(vw[4*it+0], vw[4*it+1], vw[4*it+2], vw[4*it+3]);
        }
    };

    // ---- prologue: stage 0 ----
    ldg_stage(0);
    cvt_stage();

    for (int st = 0; st < 16; st++) {
        uint32_t* buf = sh + (st & 1) * FBUF;
        sts_stage(buf);                    // write f16 tiles for stage st
        if (st < 15) ldg_stage(st + 1);    // prefetch next (latency hidden)
        __syncthreads();                   // tiles(st) visible to all warps

        const uint32_t* Kh = buf;
        const uint32_t* Vh = buf + 32 * KS;
        const uint32_t* Kbase = Kh + m4 * KS + g;   // + imm(8*k4*KS + 8*n) [+4*KS for hi]
        const uint32_t* Vbase = Vh + g * VS + m4;   // + imm(8*n*VS + 8*k4) [+4 for hi]

        // ---- mask bits ----
        uint2 m0l = *(const uint2*)(mrow0l + st * 2);
        uint2 m0h = *(const uint2*)(mrow0h + st * 2);
        uint2 m1l = *(const uint2*)(mrow1l + st * 2);
        uint2 m1h = *(const uint2*)(mrow1h + st * 2);

        // ==== 4 groups: {QK(2nb), softmax; QK(2nb+1), softmax; PV slice nb} ====
        #pragma unroll
        for (int nb = 0; nb < 4; nb++) {
            uint32_t pknb[2][2][2];

            #pragma unroll
            for (int j = 0; j < 2; j++) {
                const int n = 2 * nb + j;

                float sc[2][4] = {{0.f,0.f,0.f,0.f},{0.f,0.f,0.f,0.f}};
                #pragma unroll
                for (int k4 = 0; k4 < 4; k4++) {
                    uint32_t b0 = Kbase[8 * k4 * KS + 8 * n];
                    uint32_t b1 = Kbase[(8 * k4 + 4) * KS + 8 * n];
                    mma_f16(sc[0], qf[0][k4], b0, b1);
                    mma_f16(sc[1], qf[1][k4], b0, b1);
                }

                #pragma unroll
                for (int r = 0; r < 2; r++) {
                    uint32_t mlw = (r == 0) ? ((n < 4) ? m0l.x : m0l.y) : ((n < 4) ? m1l.x : m1l.y);
                    uint32_t mhw = (r == 0) ? ((n < 4) ? m0h.x : m0h.y) : ((n < 4) ? m1h.x : m1h.y);
                    uint32_t wl = mlw >> (2 * m4 + 8 * (n & 3));
                    uint32_t wh = mhw >> (2 * m4 + 8 * (n & 3));
                    float e00 = ex2(fmaf(sc[r][0], scale2, bias2));
                    float e01 = ex2(fmaf(sc[r][1], scale2, bias2));
                    float e10 = ex2(fmaf(sc[r][2], scale2, bias2));
                    float e11 = ex2(fmaf(sc[r][3], scale2, bias2));
                    float p00 = (wl & 1u) ? e00 : 0.f;
                    float p01 = (wl & 2u) ? e01 : 0.f;
                    float p10 = (wh & 1u) ? e10 : 0.f;
                    float p11 = (wh & 2u) ? e11 : 0.f;
                    pknb[r][j][0] = packh2(p00, p01);
                    pknb[r][j][1] = packh2(p10, p11);
                    if (r == 0) { lr[0]  += p00 + p01; lrh[0] += p10 + p11; }
                    else        { lr[1]  += p00 + p01; lrh[1] += p10 + p11; }
                }
            }

            // PV slice k4 = nb
            uint32_t a0[4] = { pknb[0][0][0], pknb[0][0][1], pknb[0][1][0], pknb[0][1][1] };
            uint32_t a1[4] = { pknb[1][0][0], pknb[1][0][1], pknb[1][1][0], pknb[1][1][1] };
            #pragma unroll
            for (int n = 0; n < 8; n++) {
                uint32_t b0 = Vbase[8 * n * VS + 8 * nb];
                uint32_t b1 = Vbase[8 * n * VS + 8 * nb + 4];
                mma_f16(o[0][n], a0, b0, b1);
                mma_f16(o[1][n], a1, b0, b1);
            }
        }

        if (st < 15) cvt_stage();   // convert prefetched f32 -> f16 regs for st+1
    }

    // ---- deferred row-sum reduction ----
    #pragma unroll
    for (int r = 0; r < 2; r++) {
        lr[r]  += __shfl_xor_sync(0xffffffffu, lr[r], 1);
        lr[r]  += __shfl_xor_sync(0xffffffffu, lr[r], 2);
        lrh[r] += __shfl_xor_sync(0xffffffffu, lrh[r], 1);
        lrh[r] += __shfl_xor_sync(0xffffffffu, lrh[r], 2);
    }

    float* ob = out + (size_t)bh * 64 * T_DIM;
    #pragma unroll
    for (int r = 0; r < 2; r++) {
        float il0 = 1.f / lr[r];
        float il1 = 1.f / lrh[r];
        #pragma unroll
        for (int n = 0; n < 8; n++) {
            int c = 8 * n + 2 * m4;
            int t = t0 + 16 * r + g;
            ob[(size_t)c       * T_DIM + t]     = o[r][n][0] * il0;
            ob[(size_t)(c + 1) * T_DIM + t]     = o[r][n][1] * il0;
            ob[(size_t)c       * T_DIM + t + 8] = o[r][n][2] * il1;
            ob[(size_t)(c + 1) * T_DIM + t + 8] = o[r][n][3] * il1;
        }
    }
}

extern "C" void kernel_launch(void* const* d_in, const int* in_sizes, int n_in,
                              void* d_out, int out_size) {
    const float* qkv = (const float*)d_in[0];
    const int* mask = (const int*)d_in[1];
    const float* bias = (const float*)d_in[2];
    float* out = (float*)d_out;

    pack_mask_bits_kernel<<<1024, 256>>>(mask);

    const int dyn_smem = 2 * FBUF * 4;   // 36,864 B per CTA
    static int attr_set = 0;
    if (!attr_set) {
        cudaFuncSetAttribute(attn_flash_kernel,
                             cudaFuncAttributeMaxDynamicSharedMemorySize, dyn_smem);
        attr_set = 1;
    }
    dim3 grid(T_DIM / BT, 8 * 16);
    attn_flash_kernel<<<grid, 128, dyn_smem>>>(qkv, bias, out);
}

// round 16
// speedup vs baseline: 1.3356x; 1.3356x over previous
#include <cuda_runtime.h>
#include <cuda_fp16.h>
#include <cstdint>

#define T_DIM 1024
#define BT 128
#define BS 64
#define KS 72            // Kh f16x2 tile stride (u32): QK frag banks 8*m4+g distinct
#define VS 36            // Vh f16x2 tile stride (u32): PV frag banks 4*g+m4 distinct
#define FBUF (32 * KS + 64 * VS)   // 4608 u32 per f16 buffer

// pre-converted fp16 operands + bit-packed mask (static device scratch)
__device__ __align__(16) uint32_t g_K16[128u * 32u * 1024u];  // [bh][c2][s]   16 MB
__device__ __align__(16) uint32_t g_V16[128u * 64u * 512u];   // [bh][c][s2]   16 MB
__device__ __align__(16) uint32_t g_maskbits[8u * 1024u * 32u];

__device__ __forceinline__ float ex2(float x) {
    float r; asm("ex2.approx.f32 %0, %1;" : "=f"(r) : "f"(x)); return r;
}
__device__ __forceinline__ uint32_t packh2(float lo, float hi) {
    __half2 h = __floats2half2_rn(lo, hi);   // .x = lo (low 16 bits)
    return *(uint32_t*)&h;
}
__device__ __forceinline__ void cp16(uint32_t dst, const void* src) {
    asm volatile("cp.async.cg.shared.global [%0], [%1], 16;" :: "r"(dst), "l"(src));
}

__device__ __forceinline__ void mma_f16(float d[4], const uint32_t a[4],
                                        uint32_t b0, uint32_t b1) {
    asm volatile(
        "mma.sync.aligned.m16n8k16.row.col.f32.f16.f16.f32 "
        "{%0,%1,%2,%3}, {%4,%5,%6,%7}, {%8,%9}, {%0,%1,%2,%3};\n"
        : "+f"(d[0]), "+f"(d[1]), "+f"(d[2]), "+f"(d[3])
        : "r"(a[0]), "r"(a[1]), "r"(a[2]), "r"(a[3]), "r"(b0), "r"(b1));
}

// ---------------- mask pre-pack (int32 -> bits) ----------------
__global__ void pack_mask_bits_kernel(const int* __restrict__ m) {
    uint32_t w = blockIdx.x * 256 + threadIdx.x;
    const int4* p = (const int4*)(m + (size_t)w * 32);
    uint32_t bits = 0;
    #pragma unroll
    for (int j = 0; j < 8; j++) {
        int4 v = p[j];
        bits |= (v.x != 0 ? 1u : 0u) << (4 * j + 0);
        bits |= (v.y != 0 ? 1u : 0u) << (4 * j + 1);
        bits |= (v.z != 0 ? 1u : 0u) << (4 * j + 2);
        bits |= (v.w != 0 ? 1u : 0u) << (4 * j + 3);
    }
    g_maskbits[w] = bits;
}

// ---------------- K/V f32 -> paired f16 pre-conversion ----------------
// blocks [0, 4096): K   (bh = b>>5, c2 = b&31), 256 thr, thread: s0 = tid*4
// blocks [4096, 12288): V (bh = (b-4096)>>6, c = (b-4096)&63), thread: s = tid*4
__global__ void convert_kv_kernel(const float* __restrict__ qkv) {
    const float SC = 0.125f * 1.4426950408889634f;   // fold qk scale (log2 domain) into K
    int b = blockIdx.x;
    int tid = threadIdx.x;
    if (b < 4096) {
        int bh = b >> 5, c2 = b & 31;
        const float* kp = qkv + (size_t)bh * 192 * T_DIM + 64 * T_DIM;
        int s0 = tid * 4;
        float4 k0 = *(const float4*)(kp + (size_t)(2 * c2) * T_DIM + s0);
        float4 k1 = *(const float4*)(kp + (size_t)(2 * c2 + 1) * T_DIM + s0);
        uint4 w;
        w.x = packh2(SC * k0.x, SC * k1.x);
        w.y = packh2(SC * k0.y, SC * k1.y);
        w.z = packh2(SC * k0.z, SC * k1.z);
        w.w = packh2(SC * k0.w, SC * k1.w);
        *(uint4*)&g_K16[(size_t)bh * 32768 + (size_t)c2 * 1024 + s0] = w;
    } else {
        int b2 = b - 4096;
        int bh = b2 >> 6, c = b2 & 63;
        const float* vp = qkv + (size_t)bh * 192 * T_DIM + 128 * T_DIM;
        int s0 = tid * 4;
        float4 v4 = *(const float4*)(vp + (size_t)c * T_DIM + s0);
        uint2 w;
        w.x = packh2(v4.x, v4.y);
        w.y = packh2(v4.z, v4.w);
        *(uint2*)&g_V16[(size_t)bh * 32768 + (size_t)c * 512 + 2 * tid] = w;
    }
}

__global__ __launch_bounds__(128, 2) void attn_flash_kernel(
    const float* __restrict__ qkv,
    float* __restrict__ out)
{
    extern __shared__ __align__(16) uint32_t sh[];   // 2 x FBUF u32

    const int tid = threadIdx.x;
    const int lane = tid & 31;
    const int g = lane >> 2;
    const int m4 = lane & 3;

    const int tile_t = blockIdx.x;   // 0..7
    const int bh = blockIdx.y;       // 0..127

    const float* qp = qkv + (size_t)bh * 192 * T_DIM;
    const uint32_t* Kg = g_K16 + (size_t)bh * 32768;
    const uint32_t* Vg = g_V16 + (size_t)bh * 32768;
    const uint32_t* mb = g_maskbits + (size_t)(bh & 7) * 1024u * 32u;

    const int t0 = tile_t * BT + (tid >> 5) * 32;

    // mask row bases (fixed across stages)
    const uint32_t* mrow0l = mb + (size_t)(t0 + g) * 32;
    const uint32_t* mrow0h = mb + (size_t)(t0 + g + 8) * 32;
    const uint32_t* mrow1l = mb + (size_t)(t0 + 16 + g) * 32;
    const uint32_t* mrow1h = mb + (size_t)(t0 + 24 + g) * 32;

    // ---- Q fragments (fp16 m16n8k16 A layout), loaded once ----
    uint32_t qf[2][4][4];
    #pragma unroll
    for (int r = 0; r < 2; r++) {
        const int t = t0 + 16 * r + g;
        #pragma unroll
        for (int k4 = 0; k4 < 4; k4++) {
            const int c0 = 16 * k4 + 2 * m4;
            qf[r][k4][0] = packh2(qp[(size_t)c0 * T_DIM + t],           qp[(size_t)(c0 + 1) * T_DIM + t]);
            qf[r][k4][1] = packh2(qp[(size_t)c0 * T_DIM + t + 8],       qp[(size_t)(c0 + 1) * T_DIM + t + 8]);
            qf[r][k4][2] = packh2(qp[(size_t)(c0 + 8) * T_DIM + t],     qp[(size_t)(c0 + 9) * T_DIM + t]);
            qf[r][k4][3] = packh2(qp[(size_t)(c0 + 8) * T_DIM + t + 8], qp[(size_t)(c0 + 9) * T_DIM + t + 8]);
        }
    }

    float o[2][8][4];
    #pragma unroll
    for (int r = 0; r < 2; r++)
        #pragma unroll
        for (int n = 0; n < 8; n++)
            { o[r][n][0]=0.f; o[r][n][1]=0.f; o[r][n][2]=0.f; o[r][n][3]=0.f; }
    float lr[2]  = {0.f, 0.f};
    float lrh[2] = {0.f, 0.f};

    const uint32_t smem_base = (uint32_t)__cvta_generic_to_shared(sh);

    // ---- staging issuer: f16 K/V tiles for stage stg -> buf stg&1 (8 cp16/thread) ----
    auto issue_stage = [&](int stg) {
        const uint32_t base = smem_base + (uint32_t)((stg & 1) * FBUF) * 4;
        #pragma unroll
        for (int it = 0; it < 4; it++) {        // K: 512 chunks
            int id = tid + it * 128;
            int c2 = id >> 4;
            int j4 = (id & 15) * 4;
            cp16(base + (uint32_t)(c2 * KS + j4) * 4,
                 Kg + (size_t)c2 * 1024 + stg * 64 + j4);
        }
        #pragma unroll
        for (int it = 0; it < 4; it++) {        // V: 512 chunks
            int id = tid + it * 128;
            int c = id >> 3;
            int j4 = (id & 7) * 4;
            cp16(base + (uint32_t)(32 * KS + c * VS + j4) * 4,
                 Vg + (size_t)c * 512 + stg * 32 + j4);
        }
        asm volatile("cp.async.commit_group;" ::: "memory");
    };

    issue_stage(0);

    for (int st = 0; st < 16; st++) {
        asm volatile("cp.async.wait_group 0;" ::: "memory");
        __syncthreads();   // buf(st) ready; reads of buf(st-1) complete

        if (st < 15) issue_stage(st + 1);

        const uint32_t* Kh = sh + (st & 1) * FBUF;
        const uint32_t* Vh = Kh + 32 * KS;

        // ---- hoisted mask bit loads ----
        uint2 m0l = *(const uint2*)(mrow0l + st * 2);
        uint2 m0h = *(const uint2*)(mrow0h + st * 2);
        uint2 m1l = *(const uint2*)(mrow1l + st * 2);
        uint2 m1h = *(const uint2*)(mrow1h + st * 2);

        // ---- S = Q^T K : 1 LDS.32 per fragment, zero cvt ----
        float sacc[2][8][4];
        #pragma unroll
        for (int r = 0; r < 2; r++)
            #pragma unroll
            for (int n = 0; n < 8; n++)
                { sacc[r][n][0]=0.f; sacc[r][n][1]=0.f; sacc[r][n][2]=0.f; sacc[r][n][3]=0.f; }
        #pragma unroll
        for (int k4 = 0; k4 < 4; k4++) {
            const uint32_t* kr0 = &Kh[(8 * k4 + m4) * KS];
            const uint32_t* kr1 = kr0 + 4 * KS;
            #pragma unroll
            for (int n = 0; n < 8; n++) {
                uint32_t b0 = kr0[8 * n + g];
                uint32_t b1 = kr1[8 * n + g];
                mma_f16(sacc[0][n], qf[0][k4], b0, b1);
                mma_f16(sacc[1][n], qf[1][k4], b0, b1);
            }
        }

        // ---- mask + exp2 (scale folded into K; bias cancels in softmax) ----
        #pragma unroll
        for (int r = 0; r < 2; r++) {
            uint2 ml = (r == 0) ? m0l : m1l;
            uint2 mh = (r == 0) ? m0h : m1h;
            uint32_t lx = ml.x >> (2 * m4), ly = ml.y >> (2 * m4);
            uint32_t hx = mh.x >> (2 * m4), hy = mh.y >> (2 * m4);
            #pragma unroll
            for (int n = 0; n < 8; n++) {
                uint32_t wl = ((n < 4) ? lx : ly) >> (8 * (n & 3));
                uint32_t wh = ((n < 4) ? hx : hy) >> (8 * (n & 3));
                float e00 = ex2(sacc[r][n][0]);
                float e01 = ex2(sacc[r][n][1]);
                float e10 = ex2(sacc[r][n][2]);
                float e11 = ex2(sacc[r][n][3]);
                float p00 = (wl & 1u) ? e00 : 0.f;
                float p01 = (wl & 2u) ? e01 : 0.f;
                float p10 = (wh & 1u) ? e10 : 0.f;
                float p11 = (wh & 2u) ? e11 : 0.f;
                sacc[r][n][0] = p00; sacc[r][n][1] = p01;
                sacc[r][n][2] = p10; sacc[r][n][3] = p11;
                lr[r]  += p00 + p01;
                lrh[r] += p10 + p11;
            }
        }

        // ---- O += P V^T : 2 LDS.32 per (k4,n), zero cvt ----
        #pragma unroll
        for (int k4 = 0; k4 < 4; k4++) {
            uint32_t a0[4], a1[4];
            a0[0] = packh2(sacc[0][2 * k4][0],     sacc[0][2 * k4][1]);
            a0[1] = packh2(sacc[0][2 * k4][2],     sacc[0][2 * k4][3]);
            a0[2] = packh2(sacc[0][2 * k4 + 1][0], sacc[0][2 * k4 + 1][1]);
            a0[3] = packh2(sacc[0][2 * k4 + 1][2], sacc[0][2 * k4 + 1][3]);
            a1[0] = packh2(sacc[1][2 * k4][0],     sacc[1][2 * k4][1]);
            a1[1] = packh2(sacc[1][2 * k4][2],     sacc[1][2 * k4][3]);
            a1[2] = packh2(sacc[1][2 * k4 + 1][0], sacc[1][2 * k4 + 1][1]);
            a1[3] = packh2(sacc[1][2 * k4 + 1][2], sacc[1][2 * k4 + 1][3]);
            #pragma unroll
            for (int n = 0; n < 8; n++) {
                const uint32_t* vr = &Vh[(8 * n + g) * VS + 8 * k4 + m4];
                uint32_t b0 = vr[0];
                uint32_t b1 = vr[4];
                mma_f16(o[0][n], a0, b0, b1);
                mma_f16(o[1][n], a1, b0, b1);
            }
        }
    }

    // ---- deferred row-sum reduction ----
    #pragma unroll
    for (int r = 0; r < 2; r++) {
        lr[r]  += __shfl_xor_sync(0xffffffffu, lr[r], 1);
        lr[r]  += __shfl_xor_sync(0xffffffffu, lr[r], 2);
        lrh[r] += __shfl_xor_sync(0xffffffffu, lrh[r], 1);
        lrh[r] += __shfl_xor_sync(0xffffffffu, lrh[r], 2);
    }

    float* ob = out + (size_t)bh * 64 * T_DIM;
    #pragma unroll
    for (int r = 0; r < 2; r++) {
        float il0 = 1.f / lr[r];
        float il1 = 1.f / lrh[r];
        #pragma unroll
        for (int n = 0; n < 8; n++) {
            int c = 8 * n + 2 * m4;
            int t = t0 + 16 * r + g;
            ob[(size_t)c       * T_DIM + t]     = o[r][n][0] * il0;
            ob[(size_t)(c + 1) * T_DIM + t]     = o[r][n][1] * il0;
            ob[(size_t)c       * T_DIM + t + 8] = o[r][n][2] * il1;
            ob[(size_t)(c + 1) * T_DIM + t + 8] = o[r][n][3] * il1;
        }
    }
}

extern "C" void kernel_launch(void* const* d_in, const int* in_sizes, int n_in,
                              void* d_out, int out_size) {
    const float* qkv = (const float*)d_in[0];
    const int* mask = (const int*)d_in[1];
    float* out = (float*)d_out;

    pack_mask_bits_kernel<<<1024, 256>>>(mask);
    convert_kv_kernel<<<12288, 256>>>(qkv);

    const int dyn_smem = 2 * FBUF * 4;   // 36,864 B per CTA
    static int attr_set = 0;
    if (!attr_set) {
        cudaFuncSetAttribute(attn_flash_kernel,
                             cudaFuncAttributeMaxDynamicSharedMemorySize, dyn_smem);
        attr_set = 1;
    }
    dim3 grid(T_DIM / BT, 8 * 16);
    attn_flash_kernel<<<grid, 128, dyn_smem>>>(qkv, out);
}

// round 17
// speedup vs baseline: 1.3722x; 1.0274x over previous
#include <cuda_runtime.h>
#include <cuda_fp16.h>
#include <cstdint>

#define T_DIM 1024
#define BT 128
#define KS 72            // Kh f16x2 tile stride (u32): QK frag banks 8*m4+g distinct
#define VS 36            // Vh f16x2 tile stride (u32): PV frag banks 4*g+m4 distinct
#define FBUF (32 * KS + 64 * VS)   // 4608 u32 per f16 buffer

// pre-converted fp16 operands + bit-packed mask (static device scratch)
__device__ __align__(16) uint32_t g_K16[128u * 32u * 1024u];  // [bh][c2][s]   16 MB
__device__ __align__(16) uint32_t g_V16[128u * 64u * 512u];   // [bh][c][s2]   16 MB
__device__ __align__(16) uint32_t g_maskbits[8u * 1024u * 32u];

__device__ __forceinline__ float ex2(float x) {
    float r; asm("ex2.approx.f32 %0, %1;" : "=f"(r) : "f"(x)); return r;
}
__device__ __forceinline__ uint32_t packh2(float lo, float hi) {
    __half2 h = __floats2half2_rn(lo, hi);   // .x = lo (low 16 bits)
    return *(uint32_t*)&h;
}
__device__ __forceinline__ void cp16(uint32_t dst, const void* src) {
    asm volatile("cp.async.cg.shared.global [%0], [%1], 16;" :: "r"(dst), "l"(src));
}

__device__ __forceinline__ void mma_f16(float d[4], const uint32_t a[4],
                                        uint32_t b0, uint32_t b1) {
    asm volatile(
        "mma.sync.aligned.m16n8k16.row.col.f32.f16.f16.f32 "
        "{%0,%1,%2,%3}, {%4,%5,%6,%7}, {%8,%9}, {%0,%1,%2,%3};\n"
        : "+f"(d[0]), "+f"(d[1]), "+f"(d[2]), "+f"(d[3])
        : "r"(a[0]), "r"(a[1]), "r"(a[2]), "r"(a[3]), "r"(b0), "r"(b1));
}

// ---------------- fused pre-pass: mask bits + K/V f16 conversion, MLP >= 8 ----------------
// blocks [0, 256):        mask pack   (4 independent int4 loads / thread)
// blocks [256, 768):      K convert   (16 independent float4 loads / thread, unrolled)
// blocks [768, 1792):     V convert   (8 independent float4 loads / thread, unrolled)
__global__ __launch_bounds__(256) void prepass_kernel(const float* __restrict__ qkv,
                                                      const int* __restrict__ mask) {
    const float SC = 0.125f * 1.4426950408889634f;   // qk scale in log2 domain, folded into K
    const int b = blockIdx.x;
    const int tid = threadIdx.x;

    if (b < 256) {
        // ---- mask: words w = b*1024 + tid + 256*j ----
        uint32_t wbase = (uint32_t)b * 1024 + tid;
        int4 v[4][8];
        #pragma unroll
        for (int j = 0; j < 4; j++) {
            const int4* p = (const int4*)(mask + (size_t)(wbase + 256 * j) * 32);
            #pragma unroll
            for (int q = 0; q < 8; q++) v[j][q] = p[q];
        }
        #pragma unroll
        for (int j = 0; j < 4; j++) {
            uint32_t bits = 0;
            #pragma unroll
            for (int q = 0; q < 8; q++) {
                bits |= (v[j][q].x != 0 ? 1u : 0u) << (4 * q + 0);
                bits |= (v[j][q].y != 0 ? 1u : 0u) << (4 * q + 1);
                bits |= (v[j][q].z != 0 ? 1u : 0u) << (4 * q + 2);
                bits |= (v[j][q].w != 0 ? 1u : 0u) << (4 * q + 3);
            }
            g_maskbits[wbase + 256 * j] = bits;
        }
    } else if (b < 768) {
        // ---- K: bh = (b-256)>>2, c2 = ((b-256)&3)*8 + tid>>5, s = lane*4 + 128*j ----
        int bb = b - 256;
        int bh = bb >> 2;
        int c2 = (bb & 3) * 8 + (tid >> 5);
        int lane = tid & 31;
        const float* kp = qkv + (size_t)bh * 192 * T_DIM + 64 * T_DIM;
        const float* r0 = kp + (size_t)(2 * c2) * T_DIM;
        const float* r1 = r0 + T_DIM;
        float4 k0[8], k1[8];
        #pragma unroll
        for (int j = 0; j < 8; j++) {
            int s0 = lane * 4 + 128 * j;
            k0[j] = *(const float4*)(r0 + s0);
            k1[j] = *(const float4*)(r1 + s0);
        }
        uint32_t* dst = &g_K16[(size_t)bh * 32768 + (size_t)c2 * 1024];
        #pragma unroll
        for (int j = 0; j < 8; j++) {
            int s0 = lane * 4 + 128 * j;
            uint4 w;
            w.x = packh2(SC * k0[j].x, SC * k1[j].x);
            w.y = packh2(SC * k0[j].y, SC * k1[j].y);
            w.z = packh2(SC * k0[j].z, SC * k1[j].z);
            w.w = packh2(SC * k0[j].w, SC * k1[j].w);
            *(uint4*)&dst[s0] = w;
        }
    } else {
        // ---- V: bh = (b-768)>>3, c = ((b-768)&7)*8 + tid>>5, s = lane*8 + 256*j ----
        int bb = b - 768;
        int bh = bb >> 3;
        int c = (bb & 7) * 8 + (tid >> 5);
        int lane = tid & 31;
        const float* vr = qkv + (size_t)bh * 192 * T_DIM + (size_t)(128 + c) * T_DIM;
        float4 vA[4], vB[4];
        #pragma unroll
        for (int j = 0; j < 4; j++) {
            int s0 = lane * 8 + 256 * j;
            vA[j] = *(const float4*)(vr + s0);
            vB[j] = *(const float4*)(vr + s0 + 4);
        }
        uint32_t* dst = &g_V16[(size_t)bh * 32768 + (size_t)c * 512];
        #pragma unroll
        for (int j = 0; j < 4; j++) {
            int s0 = lane * 8 + 256 * j;
            uint4 w;
            w.x = packh2(vA[j].x, vA[j].y);
            w.y = packh2(vA[j].z, vA[j].w);
            w.z = packh2(vB[j].x, vB[j].y);
            w.w = packh2(vB[j].z, vB[j].w);
            *(uint4*)&dst[s0 / 2] = w;
        }
    }
}

__global__ __launch_bounds__(128, 2) void attn_flash_kernel(
    const float* __restrict__ qkv,
    float* __restrict__ out)
{
    extern __shared__ __align__(16) uint32_t sh[];   // 2 x FBUF u32

    const int tid = threadIdx.x;
    const int lane = tid & 31;
    const int g = lane >> 2;
    const int m4 = lane & 3;

    const int tile_t = blockIdx.x;   // 0..7
    const int bh = blockIdx.y;       // 0..127

    const float* qp = qkv + (size_t)bh * 192 * T_DIM;
    const uint32_t* Kg = g_K16 + (size_t)bh * 32768;
    const uint32_t* Vg = g_V16 + (size_t)bh * 32768;
    const uint32_t* mb = g_maskbits + (size_t)(bh & 7) * 1024u * 32u;

    const int t0 = tile_t * BT + (tid >> 5) * 32;

    // mask row bases (fixed across stages)
    const uint32_t* mrow0l = mb + (size_t)(t0 + g) * 32;
    const uint32_t* mrow0h = mb + (size_t)(t0 + g + 8) * 32;
    const uint32_t* mrow1l = mb + (size_t)(t0 + 16 + g) * 32;
    const uint32_t* mrow1h = mb + (size_t)(t0 + 24 + g) * 32;

    // ---- Q fragments (fp16 m16n8k16 A layout), loaded once ----
    uint32_t qf[2][4][4];
    #pragma unroll
    for (int r = 0; r < 2; r++) {
        const int t = t0 + 16 * r + g;
        #pragma unroll
        for (int k4 = 0; k4 < 4; k4++) {
            const int c0 = 16 * k4 + 2 * m4;
            qf[r][k4][0] = packh2(qp[(size_t)c0 * T_DIM + t],           qp[(size_t)(c0 + 1) * T_DIM + t]);
            qf[r][k4][1] = packh2(qp[(size_t)c0 * T_DIM + t + 8],       qp[(size_t)(c0 + 1) * T_DIM + t + 8]);
            qf[r][k4][2] = packh2(qp[(size_t)(c0 + 8) * T_DIM + t],     qp[(size_t)(c0 + 9) * T_DIM + t]);
            qf[r][k4][3] = packh2(qp[(size_t)(c0 + 8) * T_DIM + t + 8], qp[(size_t)(c0 + 9) * T_DIM + t + 8]);
        }
    }

    float o[2][8][4];
    #pragma unroll
    for (int r = 0; r < 2; r++)
        #pragma unroll
        for (int n = 0; n < 8; n++)
            { o[r][n][0]=0.f; o[r][n][1]=0.f; o[r][n][2]=0.f; o[r][n][3]=0.f; }
    float lr[2]  = {0.f, 0.f};
    float lrh[2] = {0.f, 0.f};

    const uint32_t smem_base = (uint32_t)__cvta_generic_to_shared(sh);

    // ---- staging issuer: f16 K/V tiles for stage stg -> buf stg&1 (8 cp16/thread) ----
    auto issue_stage = [&](int stg) {
        const uint32_t base = smem_base + (uint32_t)((stg & 1) * FBUF) * 4;
        #pragma unroll
        for (int it = 0; it < 4; it++) {        // K: 512 chunks
            int id = tid + it * 128;
            int c2 = id >> 4;
            int j4 = (id & 15) * 4;
            cp16(base + (uint32_t)(c2 * KS + j4) * 4,
                 Kg + (size_t)c2 * 1024 + stg * 64 + j4);
        }
        #pragma unroll
        for (int it = 0; it < 4; it++) {        // V: 512 chunks
            int id = tid + it * 128;
            int c = id >> 3;
            int j4 = (id & 7) * 4;
            cp16(base + (uint32_t)(32 * KS + c * VS + j4) * 4,
                 Vg + (size_t)c * 512 + stg * 32 + j4);
        }
        asm volatile("cp.async.commit_group;" ::: "memory");
    };

    issue_stage(0);

    for (int st = 0; st < 16; st++) {
        asm volatile("cp.async.wait_group 0;" ::: "memory");
        __syncthreads();   // buf(st) ready; reads of buf(st-1) complete

        if (st < 15) issue_stage(st + 1);

        const uint32_t* Kh = sh + (st & 1) * FBUF;
        const uint32_t* Vh = Kh + 32 * KS;

        // ---- hoisted mask bit loads ----
        uint2 m0l = *(const uint2*)(mrow0l + st * 2);
        uint2 m0h = *(const uint2*)(mrow0h + st * 2);
        uint2 m1l = *(const uint2*)(mrow1l + st * 2);
        uint2 m1h = *(const uint2*)(mrow1h + st * 2);

        // ---- S = Q^T K : 1 LDS.32 per fragment, zero cvt ----
        float sacc[2][8][4];
        #pragma unroll
        for (int r = 0; r < 2; r++)
            #pragma unroll
            for (int n = 0; n < 8; n++)
                { sacc[r][n][0]=0.f; sacc[r][n][1]=0.f; sacc[r][n][2]=0.f; sacc[r][n][3]=0.f; }
        #pragma unroll
        for (int k4 = 0; k4 < 4; k4++) {
            const uint32_t* kr0 = &Kh[(8 * k4 + m4) * KS];
            const uint32_t* kr1 = kr0 + 4 * KS;
            #pragma unroll
            for (int n = 0; n < 8; n++) {
                uint32_t b0 = kr0[8 * n + g];
                uint32_t b1 = kr1[8 * n + g];
                mma_f16(sacc[0][n], qf[0][k4], b0, b1);
                mma_f16(sacc[1][n], qf[1][k4], b0, b1);
            }
        }

        // ---- mask + exp2 (scale folded into K; bias cancels in softmax) ----
        #pragma unroll
        for (int r = 0; r < 2; r++) {
            uint2 ml = (r == 0) ? m0l : m1l;
            uint2 mh = (r == 0) ? m0h : m1h;
            uint32_t lx = ml.x >> (2 * m4), ly = ml.y >> (2 * m4);
            uint32_t hx = mh.x >> (2 * m4), hy = mh.y >> (2 * m4);
            #pragma unroll
            for (int n = 0; n < 8; n++) {
                uint32_t wl = ((n < 4) ? lx : ly) >> (8 * (n & 3));
                uint32_t wh = ((n < 4) ? hx : hy) >> (8 * (n & 3));
                float e00 = ex2(sacc[r][n][0]);
                float e01 = ex2(sacc[r][n][1]);
                float e10 = ex2(sacc[r][n][2]);
                float e11 = ex2(sacc[r][n][3]);
                float p00 = (wl & 1u) ? e00 : 0.f;
                float p01 = (wl & 2u) ? e01 : 0.f;
                float p10 = (wh & 1u) ? e10 : 0.f;
                float p11 = (wh & 2u) ? e11 : 0.f;
                sacc[r][n][0] = p00; sacc[r][n][1] = p01;
                sacc[r][n][2] = p10; sacc[r][n][3] = p11;
                lr[r]  += p00 + p01;
                lrh[r] += p10 + p11;
            }
        }

        // ---- O += P V^T : 2 LDS.32 per (k4,n), zero cvt ----
        #pragma unroll
        for (int k4 = 0; k4 < 4; k4++) {
            uint32_t a0[4], a1[4];
            a0[0] = packh2(sacc[0][2 * k4][0],     sacc[0][2 * k4][1]);
            a0[1] = packh2(sacc[0][2 * k4][2],     sacc[0][2 * k4][3]);
            a0[2] = packh2(sacc[0][2 * k4 + 1][0], sacc[0][2 * k4 + 1][1]);
            a0[3] = packh2(sacc[0][2 * k4 + 1][2], sacc[0][2 * k4 + 1][3]);
            a1[0] = packh2(sacc[1][2 * k4][0],     sacc[1][2 * k4][1]);
            a1[1] = packh2(sacc[1][2 * k4][2],     sacc[1][2 * k4][3]);
            a1[2] = packh2(sacc[1][2 * k4 + 1][0], sacc[1][2 * k4 + 1][1]);
            a1[3] = packh2(sacc[1][2 * k4 + 1][2], sacc[1][2 * k4 + 1][3]);
            #pragma unroll
            for (int n = 0; n < 8; n++) {
                const uint32_t* vr = &Vh[(8 * n + g) * VS + 8 * k4 + m4];
                uint32_t b0 = vr[0];
                uint32_t b1 = vr[4];
                mma_f16(o[0][n], a0, b0, b1);
                mma_f16(o[1][n], a1, b0, b1);
            }
        }
    }

    // ---- deferred row-sum reduction ----
    #pragma unroll
    for (int r = 0; r < 2; r++) {
        lr[r]  += __shfl_xor_sync(0xffffffffu, lr[r], 1);
        lr[r]  += __shfl_xor_sync(0xffffffffu, lr[r], 2);
        lrh[r] += __shfl_xor_sync(0xffffffffu, lrh[r], 1);
        lrh[r] += __shfl_xor_sync(0xffffffffu, lrh[r], 2);
    }

    float* ob = out + (size_t)bh * 64 * T_DIM;
    #pragma unroll
    for (int r = 0; r < 2; r++) {
        float il0 = 1.f / lr[r];
        float il1 = 1.f / lrh[r];
        #pragma unroll
        for (int n = 0; n < 8; n++) {
            int c = 8 * n + 2 * m4;
            int t = t0 + 16 * r + g;
            ob[(size_t)c       * T_DIM + t]     = o[r][n][0] * il0;
            ob[(size_t)(c + 1) * T_DIM + t]     = o[r][n][1] * il0;
            ob[(size_t)c       * T_DIM + t + 8] = o[r][n][2] * il1;
            ob[(size_t)(c + 1) * T_DIM + t + 8] = o[r][n][3] * il1;
        }
    }
}

extern "C" void kernel_launch(void* const* d_in, const int* in_sizes, int n_in,
                              void* d_out, int out_size) {
    const float* qkv = (const float*)d_in[0];
    const int* mask = (const int*)d_in[1];
    float* out = (float*)d_out;

    prepass_kernel<<<1792, 256>>>(qkv, mask);

    const int dyn_smem = 2 * FBUF * 4;   // 36,864 B per CTA
    static int attr_set = 0;
    if (!attr_set) {
        cudaFuncSetAttribute(attn_flash_kernel,
                             cudaFuncAttributeMaxDynamicSharedMemorySize, dyn_smem);
        attr_set = 1;
    }
    dim3 grid(T_DIM / BT, 8 * 16);
    attn_flash_kernel<<<grid, 128, dyn_smem>>>(qkv, out);
}